// round 1
// baseline (speedup 1.0000x reference)
#include <cuda_runtime.h>
#include <cstdint>

#define NB 8
#define NS 4096
#define ND 128
#define NT 32           // NS / 128
#define TPITCH 129      // padded tile pitch (floats)

// ---------------- scratch (no allocations allowed) ----------------
__device__ float g_Q[NB * NS * ND];       // 16.8 MB
__device__ float g_K[NB * NS * ND];       // 16.8 MB
__device__ float g_Z[NB * NS];            // row sums of exp(scores)
__device__ float g_w[NB * NS];            // column sums of attn
__device__ float g_upart[NB * NT * ND];   // partial w^T X

// ---------------- fast exp on the FMA pipe (avoid MUFU) ----------------
__device__ __forceinline__ float fast_exp(float x) {
    // exp(x) = 2^(x * log2(e));  split into integer + fraction, poly for 2^f
    float y = x * 1.44269504088896341f;
    y = fminf(fmaxf(y, -120.0f), 120.0f);
    int   e = __float2int_rn(y);
    float f = y - (float)e;              // f in [-0.5, 0.5]
    // Taylor of 2^f = sum (ln2*f)^k/k!, degree 6: rel err ~1e-8
    const float c1 = 0.6931471805599453f;
    const float c2 = 0.2402265069591007f;
    const float c3 = 0.0555041086648216f;
    const float c4 = 0.0096181291076285f;
    const float c5 = 0.0013333558146428f;
    const float c6 = 0.0001540353039338f;
    float p = c6;
    p = fmaf(p, f, c5);
    p = fmaf(p, f, c4);
    p = fmaf(p, f, c3);
    p = fmaf(p, f, c2);
    p = fmaf(p, f, c1);
    p = fmaf(p, f, 1.0f);
    float s = __int_as_float((e + 127) << 23);
    return p * s;
}

// load a 128x128 fp32 tile (row-major, row stride 128) into smem with pitch 129
__device__ __forceinline__ void load_tile129(float* dst, const float* __restrict__ src, int tid) {
    #pragma unroll
    for (int it = 0; it < 16; ++it) {
        int idx = tid + it * 256;
        int row = idx >> 5;
        int c4  = (idx & 31) << 2;
        float4 v = *reinterpret_cast<const float4*>(src + (size_t)row * 128 + c4);
        float* p = dst + row * TPITCH + c4;
        p[0] = v.x; p[1] = v.y; p[2] = v.z; p[3] = v.w;
    }
}

// ---------------- projections: Q = X Wq, K = X Wk ----------------
// grid 256 (one 128-row tile of the flattened [B*S, D] matrix), 256 threads
__global__ void proj_kernel(const float* __restrict__ X, const float* __restrict__ Wqk) {
    extern __shared__ float sm[];
    float* Xs = sm;                 // [128][129]
    float* Ws = sm + 128 * TPITCH;  // [128][128] (d-major, e contiguous)
    const int tid = threadIdx.x, tx = tid & 15, ty = tid >> 4;
    const size_t r0 = (size_t)blockIdx.x * 128;

    load_tile129(Xs, X + r0 * 128, tid);

    for (int w = 0; w < 2; ++w) {
        const float* Wg = Wqk + (size_t)w * 128 * 128;
        #pragma unroll
        for (int it = 0; it < 16; ++it)
            reinterpret_cast<float4*>(Ws)[tid + it * 256] =
                reinterpret_cast<const float4*>(Wg)[tid + it * 256];
        __syncthreads();

        float acc[64];
        #pragma unroll
        for (int t = 0; t < 64; ++t) acc[t] = 0.0f;

        #pragma unroll 4
        for (int d = 0; d < 128; ++d) {
            float a[8], b[8];
            #pragma unroll
            for (int i = 0; i < 8; ++i) a[i] = Xs[(ty + 16 * i) * TPITCH + d];
            #pragma unroll
            for (int j = 0; j < 8; ++j) b[j] = Ws[d * 128 + tx + 16 * j];
            #pragma unroll
            for (int i = 0; i < 8; ++i)
                #pragma unroll
                for (int j = 0; j < 8; ++j)
                    acc[i * 8 + j] = fmaf(a[i], b[j], acc[i * 8 + j]);
        }
        __syncthreads();  // before next W overwrites smem

        float* Og = (w == 0) ? g_Q : g_K;
        #pragma unroll
        for (int i = 0; i < 8; ++i)
            #pragma unroll
            for (int j = 0; j < 8; ++j)
                Og[(r0 + ty + 16 * i) * 128 + tx + 16 * j] = acc[i * 8 + j];
    }
}

// ---------------- pass 1: Z[q] = sum_k exp(Q[q]·K[k]) ----------------
// grid = NB*NT (b = blk>>5, q-tile = blk&31), 256 threads
__global__ void pass1_kernel() {
    extern __shared__ float sm[];
    float* Qs = sm;                 // resident q tile [128][129]
    float* Ks = sm + 128 * TPITCH;  // streamed k tile [128][129]
    const int tid = threadIdx.x, tx = tid & 15, ty = tid >> 4;
    const int b = blockIdx.x >> 5, qt = blockIdx.x & 31;
    const float* Qg = g_Q + ((size_t)b * NS + qt * 128) * 128;
    const float* Kg = g_K + (size_t)b * NS * 128;

    load_tile129(Qs, Qg, tid);

    float zsum[8];
    #pragma unroll
    for (int i = 0; i < 8; ++i) zsum[i] = 0.0f;

    for (int kt = 0; kt < NT; ++kt) {
        load_tile129(Ks, Kg + (size_t)kt * 128 * 128, tid);
        __syncthreads();

        float acc[64];
        #pragma unroll
        for (int t = 0; t < 64; ++t) acc[t] = 0.0f;

        #pragma unroll 4
        for (int d = 0; d < 128; ++d) {
            float a[8], bb[8];
            #pragma unroll
            for (int i = 0; i < 8; ++i) a[i]  = Qs[(ty + 16 * i) * TPITCH + d];
            #pragma unroll
            for (int j = 0; j < 8; ++j) bb[j] = Ks[(tx + 16 * j) * TPITCH + d];
            #pragma unroll
            for (int i = 0; i < 8; ++i)
                #pragma unroll
                for (int j = 0; j < 8; ++j)
                    acc[i * 8 + j] = fmaf(a[i], bb[j], acc[i * 8 + j]);
        }

        #pragma unroll
        for (int i = 0; i < 8; ++i) {
            float s = 0.0f;
            #pragma unroll
            for (int j = 0; j < 8; ++j) s += fast_exp(acc[i * 8 + j]);
            zsum[i] += s;
        }
        __syncthreads();  // before streaming the next K tile
    }

    // reduce over tx (16 contiguous lanes within the warp share a q-row set)
    #pragma unroll
    for (int i = 0; i < 8; ++i) {
        float v = zsum[i];
        v += __shfl_xor_sync(0xffffffffu, v, 1);
        v += __shfl_xor_sync(0xffffffffu, v, 2);
        v += __shfl_xor_sync(0xffffffffu, v, 4);
        v += __shfl_xor_sync(0xffffffffu, v, 8);
        if (tx == 0) g_Z[b * NS + qt * 128 + ty + 16 * i] = v;
    }
}

// ---------------- pass 2: w[k] = sum_q exp(Q[q]·K[k]) / Z[q] ----------------
// grid = NB*NT (b = blk>>5, k-tile = blk&31), 256 threads
__global__ void pass2_kernel() {
    extern __shared__ float sm[];
    float* Qs = sm;                     // streamed q tile
    float* Ks = sm + 128 * TPITCH;      // resident k tile
    float* rz = sm + 2 * 128 * TPITCH;  // 128 reciprocals of Z for current q tile
    const int tid = threadIdx.x, tx = tid & 15, ty = tid >> 4;
    const int b = blockIdx.x >> 5, kt = blockIdx.x & 31;
    const float* Kg = g_K + ((size_t)b * NS + kt * 128) * 128;
    const float* Qg = g_Q + (size_t)b * NS * 128;

    load_tile129(Ks, Kg, tid);

    float wacc[8];
    #pragma unroll
    for (int j = 0; j < 8; ++j) wacc[j] = 0.0f;

    for (int qt = 0; qt < NT; ++qt) {
        load_tile129(Qs, Qg + (size_t)qt * 128 * 128, tid);
        if (tid < 128) rz[tid] = 1.0f / g_Z[b * NS + qt * 128 + tid];
        __syncthreads();

        float acc[64];
        #pragma unroll
        for (int t = 0; t < 64; ++t) acc[t] = 0.0f;

        #pragma unroll 4
        for (int d = 0; d < 128; ++d) {
            float a[8], bb[8];
            #pragma unroll
            for (int i = 0; i < 8; ++i) a[i]  = Qs[(ty + 16 * i) * TPITCH + d];
            #pragma unroll
            for (int j = 0; j < 8; ++j) bb[j] = Ks[(tx + 16 * j) * TPITCH + d];
            #pragma unroll
            for (int i = 0; i < 8; ++i)
                #pragma unroll
                for (int j = 0; j < 8; ++j)
                    acc[i * 8 + j] = fmaf(a[i], bb[j], acc[i * 8 + j]);
        }

        #pragma unroll
        for (int i = 0; i < 8; ++i) {
            float r = rz[ty + 16 * i];
            #pragma unroll
            for (int j = 0; j < 8; ++j)
                wacc[j] = fmaf(fast_exp(acc[i * 8 + j]), r, wacc[j]);
        }
        __syncthreads();
    }

    // reduce over ty via smem (reuse tile storage)
    float* red = sm;  // [128 k][16 ty]
    #pragma unroll
    for (int j = 0; j < 8; ++j) red[(tx + 16 * j) * 16 + ty] = wacc[j];
    __syncthreads();
    if (tid < 128) {
        float s = 0.0f;
        #pragma unroll
        for (int t = 0; t < 16; ++t) s += red[tid * 16 + t];
        g_w[b * NS + kt * 128 + tid] = s;
    }
}

// ---------------- u_part[b,chunk,:] = sum_{k in chunk} w[b,k] * X[b,k,:] ----------------
__global__ void accum_u_kernel(const float* __restrict__ X) {
    const int b = blockIdx.x >> 5, kc = blockIdx.x & 31;
    const int d = threadIdx.x;  // 128 threads
    const float* Xg = X + ((size_t)b * NS + kc * 128) * 128;
    const float* wg = g_w + b * NS + kc * 128;
    float s = 0.0f;
    #pragma unroll 8
    for (int k = 0; k < 128; ++k) s = fmaf(wg[k], Xg[(size_t)k * 128 + d], s);
    g_upart[((size_t)b * NT + kc) * 128 + d] = s;
}

// ---------------- out[b,:] = (u[b,:] @ Wv) / S ----------------
__global__ void out_kernel(const float* __restrict__ Wv, float* __restrict__ out) {
    const int b = blockIdx.x;
    const int e = threadIdx.x;  // 128 threads
    __shared__ float u[128];
    float us = 0.0f;
    #pragma unroll
    for (int c = 0; c < NT; ++c) us += g_upart[((size_t)b * NT + c) * 128 + threadIdx.x];
    u[threadIdx.x] = us;
    __syncthreads();
    float acc = 0.0f;
    #pragma unroll 8
    for (int d = 0; d < 128; ++d) acc = fmaf(u[d], Wv[d * 128 + e], acc);
    out[b * 128 + e] = acc * (1.0f / (float)NS);
}

// ---------------- launcher ----------------
extern "C" void kernel_launch(void* const* d_in, const int* in_sizes, int n_in,
                              void* d_out, int out_size) {
    int xi = 0, wi = 1;
    if (n_in >= 2 && in_sizes[0] == 3 * 128 * 128) { xi = 1; wi = 0; }  // order insurance
    const float* X = (const float*)d_in[xi];
    const float* W = (const float*)d_in[wi];
    float* out = (float*)d_out;

    const int SM_PROJ = (128 * TPITCH + 128 * 128) * 4;
    const int SM_PASS = (2 * 128 * TPITCH + 128) * 4;
    cudaFuncSetAttribute(proj_kernel,  cudaFuncAttributeMaxDynamicSharedMemorySize, SM_PROJ);
    cudaFuncSetAttribute(pass1_kernel, cudaFuncAttributeMaxDynamicSharedMemorySize, SM_PASS);
    cudaFuncSetAttribute(pass2_kernel, cudaFuncAttributeMaxDynamicSharedMemorySize, SM_PASS);

    proj_kernel <<<NB * NT, 256, SM_PROJ>>>(X, W);
    pass1_kernel<<<NB * NT, 256, SM_PASS>>>();
    pass2_kernel<<<NB * NT, 256, SM_PASS>>>();
    accum_u_kernel<<<NB * NT, 128>>>(X);
    out_kernel  <<<NB, 128>>>(W + 2 * 128 * 128, out);
    (void)out_size;
}

// round 3
// speedup vs baseline: 2.1996x; 2.1996x over previous
#include <cuda_runtime.h>
#include <cuda_bf16.h>
#include <cstdint>

#define NB 8
#define NS 4096
#define ND 128
#define NT 32                 // NS / 128
#define TPITCH 129            // fp32 smem pitch (proj kernel)
#define NTILES (NB * NT)      // 256 row-tiles of flattened [B*S, D]
#define TILE_ELEMS 16384      // 128*128
#define PITCHB 272            // bf16 tile smem row pitch in BYTES (136 bf16)
#define TILEB (128 * PITCHB)  // 34816 bytes per padded tile

// ---------------- scratch (static device arrays; no allocations) ----------------
__device__ __nv_bfloat16 g_Qhi[NTILES * TILE_ELEMS];
__device__ __nv_bfloat16 g_Qlo[NTILES * TILE_ELEMS];
__device__ __nv_bfloat16 g_Khi[NTILES * TILE_ELEMS];
__device__ __nv_bfloat16 g_Klo[NTILES * TILE_ELEMS];
__device__ float g_Z[NB * NS];
__device__ float g_w[NB * NS];
__device__ float g_upart[NB * NT * ND];

// ---------------- helpers ----------------
__device__ __forceinline__ uint32_t smem_u32(const void* p) {
    uint32_t a;
    asm("{ .reg .u64 t; cvta.to.shared.u64 t, %1; cvt.u32.u64 %0, t; }" : "=r"(a) : "l"(p));
    return a;
}
__device__ __forceinline__ void cpa16(uint32_t dst, const void* src) {
    asm volatile("cp.async.cg.shared.global [%0], [%1], 16;" :: "r"(dst), "l"(src));
}
__device__ __forceinline__ void cpa_commit() {
    asm volatile("cp.async.commit_group;" ::: "memory");
}
template<int N>
__device__ __forceinline__ void cpa_wait() {
    asm volatile("cp.async.wait_group %0;" :: "n"(N) : "memory");
}
__device__ __forceinline__ void ldsm_x4(uint32_t& r0, uint32_t& r1, uint32_t& r2, uint32_t& r3,
                                        uint32_t addr) {
    asm volatile("ldmatrix.sync.aligned.m8n8.x4.shared.b16 {%0,%1,%2,%3}, [%4];"
                 : "=r"(r0), "=r"(r1), "=r"(r2), "=r"(r3) : "r"(addr));
}
__device__ __forceinline__ void mma16816(float* c, const uint32_t* a, uint32_t b0, uint32_t b1) {
    asm volatile(
        "mma.sync.aligned.m16n8k16.row.col.f32.bf16.bf16.f32 "
        "{%0,%1,%2,%3}, {%4,%5,%6,%7}, {%8,%9}, {%0,%1,%2,%3};"
        : "+f"(c[0]), "+f"(c[1]), "+f"(c[2]), "+f"(c[3])
        : "r"(a[0]), "r"(a[1]), "r"(a[2]), "r"(a[3]), "r"(b0), "r"(b1));
}

// fast exp on the FMA pipe (avoid MUFU)
__device__ __forceinline__ float fast_exp(float x) {
    float y = x * 1.44269504088896341f;
    y = fminf(fmaxf(y, -120.0f), 120.0f);
    int   e = __float2int_rn(y);
    float f = y - (float)e;
    const float c1 = 0.6931471805599453f, c2 = 0.2402265069591007f;
    const float c3 = 0.0555041086648216f, c4 = 0.0096181291076285f;
    const float c5 = 0.0013333558146428f, c6 = 0.0001540353039338f;
    float p = c6;
    p = fmaf(p, f, c5); p = fmaf(p, f, c4); p = fmaf(p, f, c3);
    p = fmaf(p, f, c2); p = fmaf(p, f, c1); p = fmaf(p, f, 1.0f);
    return p * __int_as_float((e + 127) << 23);
}

__device__ __forceinline__ void load_tile129(float* dst, const float* __restrict__ src, int tid) {
    #pragma unroll
    for (int it = 0; it < 16; ++it) {
        int idx = tid + it * 256;
        int row = idx >> 5;
        int c4  = (idx & 31) << 2;
        float4 v = *reinterpret_cast<const float4*>(src + (size_t)row * 128 + c4);
        float* p = dst + row * TPITCH + c4;
        p[0] = v.x; p[1] = v.y; p[2] = v.z; p[3] = v.w;
    }
}

// ---------------- projections: fp32 GEMM -> bf16 hi/lo row-major tiles ----------------
#define SM_PROJ (128 * TPITCH * 4 + 65536)

__global__ void __launch_bounds__(256) proj_kernel(const float* __restrict__ X,
                                                   const float* __restrict__ Wqk) {
    extern __shared__ char smc[];
    float* Xs  = (float*)smc;
    float* Ws  = (float*)(smc + 128 * TPITCH * 4);
    char*  stg = smc + 128 * TPITCH * 4;     // aliases Ws after compute
    const int tid = threadIdx.x, tx = tid & 15, ty = tid >> 4;
    const size_t r0 = (size_t)blockIdx.x * 128;

    load_tile129(Xs, X + r0 * 128, tid);

    for (int w = 0; w < 2; ++w) {
        const float* Wg = Wqk + (size_t)w * TILE_ELEMS;
        #pragma unroll
        for (int it = 0; it < 16; ++it)
            reinterpret_cast<float4*>(Ws)[tid + it * 256] =
                reinterpret_cast<const float4*>(Wg)[tid + it * 256];
        __syncthreads();

        float acc[64];
        #pragma unroll
        for (int t = 0; t < 64; ++t) acc[t] = 0.0f;

        #pragma unroll 4
        for (int d = 0; d < 128; ++d) {
            float a[8], b[8];
            #pragma unroll
            for (int i = 0; i < 8; ++i) a[i] = Xs[(ty + 16 * i) * TPITCH + d];
            #pragma unroll
            for (int j = 0; j < 8; ++j) b[j] = Ws[d * 128 + tx + 16 * j];
            #pragma unroll
            for (int i = 0; i < 8; ++i)
                #pragma unroll
                for (int j = 0; j < 8; ++j)
                    acc[i * 8 + j] = fmaf(a[i], b[j], acc[i * 8 + j]);
        }
        __syncthreads();

        #pragma unroll
        for (int i = 0; i < 8; ++i)
            #pragma unroll
            for (int j = 0; j < 8; ++j) {
                float v = acc[i * 8 + j];
                __nv_bfloat16 hi = __float2bfloat16(v);
                __nv_bfloat16 lo = __float2bfloat16(v - __bfloat162float(hi));
                uint32_t o = (uint32_t)(ty + 16 * i) * 256 + (uint32_t)(tx + 16 * j) * 2;
                *(__nv_bfloat16*)(stg + o) = hi;
                *(__nv_bfloat16*)(stg + 32768 + o) = lo;
            }
        __syncthreads();

        __nv_bfloat16* dh = (w == 0 ? g_Qhi : g_Khi) + (size_t)blockIdx.x * TILE_ELEMS;
        __nv_bfloat16* dl = (w == 0 ? g_Qlo : g_Klo) + (size_t)blockIdx.x * TILE_ELEMS;
        #pragma unroll
        for (int it = 0; it < 8; ++it)
            reinterpret_cast<uint4*>(dh)[tid + it * 256] =
                reinterpret_cast<const uint4*>(stg)[tid + it * 256];
        #pragma unroll
        for (int it = 0; it < 8; ++it)
            reinterpret_cast<uint4*>(dl)[tid + it * 256] =
                reinterpret_cast<const uint4*>(stg + 32768)[tid + it * 256];
        __syncthreads();
    }
}

// ---------------- score passes via mma.sync (legacy HMMA) ----------------
// MODE 0: resident A = Q tile rt (rows q), stream K as B (cols k); Z[q] = sum exp
// MODE 1: resident A = K tile rt (rows k), stream Q as B (cols q); w[k] = sum exp/Z[q]
#define O_RHI  0
#define O_RLO  TILEB
#define O_SB(buf) (2 * TILEB + (buf) * 2 * TILEB)
#define O_RZ   (6 * TILEB)               // 208896
#define O_RED  (O_RZ + 512)              // 4 warpN * 128 rows * 4B
#define SM_SCORE (O_RED + 2048)          // 211456 bytes

// async-copy one 128x128 bf16 row-major tile into padded smem
__device__ __forceinline__ void tile_g2s(uint32_t dst, const __nv_bfloat16* src, int tid) {
    #pragma unroll
    for (int i = 0; i < 8; ++i) {
        int c = tid + i * 256;          // 2048 16B-chunks
        int row = c >> 4, col = c & 15;
        cpa16(dst + row * PITCHB + col * 16, (const char*)src + row * 256 + col * 16);
    }
}

template<int MODE>
__global__ void __launch_bounds__(256, 1) score_pass() {
    extern __shared__ char smc[];
    const uint32_t sb = smem_u32(smc);
    const int tid = threadIdx.x, lane = tid & 31, warp = tid >> 5;
    const int warpM = warp & 1, warpN = warp >> 1;   // 2 x 4 warp grid; 64x32 per warp
    const int b = blockIdx.x >> 5, rt = blockIdx.x & 31;
    const int tile0 = b * NT;

    const __nv_bfloat16* Rhi = (MODE == 0 ? g_Qhi : g_Khi) + (size_t)(tile0 + rt) * TILE_ELEMS;
    const __nv_bfloat16* Rlo = (MODE == 0 ? g_Qlo : g_Klo) + (size_t)(tile0 + rt) * TILE_ELEMS;
    const __nv_bfloat16* Shi = (MODE == 0 ? g_Khi : g_Qhi) + (size_t)tile0 * TILE_ELEMS;
    const __nv_bfloat16* Slo = (MODE == 0 ? g_Klo : g_Qlo) + (size_t)tile0 * TILE_ELEMS;

    // prologue: resident tile + first streamed tile (group A), second streamed (group B)
    tile_g2s(sb + O_RHI, Rhi, tid);
    tile_g2s(sb + O_RLO, Rlo, tid);
    tile_g2s(sb + O_SB(0), Shi, tid);
    tile_g2s(sb + O_SB(0) + TILEB, Slo, tid);
    cpa_commit();
    tile_g2s(sb + O_SB(1), Shi + TILE_ELEMS, tid);
    tile_g2s(sb + O_SB(1) + TILEB, Slo + TILE_ELEMS, tid);
    cpa_commit();

    // per-lane ldmatrix byte offsets
    const uint32_t a_off = (uint32_t)(warpM * 64 + (lane & 15)) * PITCHB + (lane >> 4) * 16;
    const uint32_t b_off = (uint32_t)(warpN * 32 + (lane & 15)) * PITCHB + (lane >> 4) * 16;

    float* rz = (float*)(smc + O_RZ);
    float zp[8];
    #pragma unroll
    for (int i = 0; i < 8; ++i) zp[i] = 0.0f;

    for (int kt = 0; kt < NT; ++kt) {
        cpa_wait<1>();
        if (MODE == 1 && tid < 128) rz[tid] = 1.0f / g_Z[b * NS + kt * 128 + tid];
        __syncthreads();

        float rzv[8];
        if (MODE == 1) {
            #pragma unroll
            for (int nt = 0; nt < 4; ++nt) {
                rzv[nt * 2 + 0] = rz[warpN * 32 + nt * 8 + 2 * (lane & 3)];
                rzv[nt * 2 + 1] = rz[warpN * 32 + nt * 8 + 2 * (lane & 3) + 1];
            }
        }

        float acc[16][4];
        #pragma unroll
        for (int t = 0; t < 16; ++t)
            #pragma unroll
            for (int r = 0; r < 4; ++r) acc[t][r] = 0.0f;

        const uint32_t sbuf = sb + O_SB(kt & 1);
        // split combos: (A,B) in {(hi,hi),(hi,lo),(lo,hi)}
        #pragma unroll
        for (int sp = 0; sp < 3; ++sp) {
            const uint32_t abase = sb + (sp == 2 ? O_RLO : O_RHI) + a_off;
            const uint32_t bbase = sbuf + (sp == 1 ? TILEB : 0) + b_off;
            #pragma unroll
            for (int ks = 0; ks < 8; ++ks) {
                uint32_t a[4][4];
                #pragma unroll
                for (int mt = 0; mt < 4; ++mt)
                    ldsm_x4(a[mt][0], a[mt][1], a[mt][2], a[mt][3],
                            abase + mt * 16 * PITCHB + ks * 32);
                uint32_t bb[4][2];
                #pragma unroll
                for (int nt2 = 0; nt2 < 2; ++nt2) {
                    uint32_t r0, r1, r2, r3;
                    ldsm_x4(r0, r1, r2, r3, bbase + nt2 * 16 * PITCHB + ks * 32);
                    bb[nt2 * 2 + 0][0] = r0; bb[nt2 * 2 + 0][1] = r2;
                    bb[nt2 * 2 + 1][0] = r1; bb[nt2 * 2 + 1][1] = r3;
                }
                #pragma unroll
                for (int mt = 0; mt < 4; ++mt)
                    #pragma unroll
                    for (int nt = 0; nt < 4; ++nt)
                        mma16816(acc[mt * 4 + nt], a[mt], bb[nt][0], bb[nt][1]);
            }
        }
        __syncthreads();                  // everyone done with ldmatrix on buf[kt&1]
        if (kt + 2 < NT) {
            tile_g2s(sb + O_SB(kt & 1),         Shi + (size_t)(kt + 2) * TILE_ELEMS, tid);
            tile_g2s(sb + O_SB(kt & 1) + TILEB, Slo + (size_t)(kt + 2) * TILE_ELEMS, tid);
            cpa_commit();
        } else {
            cpa_commit();                 // keep group count in lockstep for wait<1>
        }

        // epilogue: exp (+ optional 1/Z weight), reduce over cols within fragment rows
        #pragma unroll
        for (int mt = 0; mt < 4; ++mt)
            #pragma unroll
            for (int p = 0; p < 2; ++p) {
                float s = 0.0f;
                #pragma unroll
                for (int nt = 0; nt < 4; ++nt)
                    #pragma unroll
                    for (int par = 0; par < 2; ++par) {
                        float e = fast_exp(acc[mt * 4 + nt][p * 2 + par]);
                        s += (MODE == 0) ? e : e * rzv[nt * 2 + par];
                    }
                zp[mt * 2 + p] += s;
            }
    }

    // lane reduction over column quads, then cross-warpN via smem
    float* red = (float*)(smc + O_RED);
    #pragma unroll
    for (int i = 0; i < 8; ++i) {
        float v = zp[i];
        v += __shfl_xor_sync(0xffffffffu, v, 1);
        v += __shfl_xor_sync(0xffffffffu, v, 2);
        int mt = i >> 1, p = i & 1;
        if ((lane & 3) == 0)
            red[warpN * 128 + warpM * 64 + mt * 16 + p * 8 + (lane >> 2)] = v;
    }
    __syncthreads();
    if (tid < 128) {
        float s = red[tid] + red[128 + tid] + red[256 + tid] + red[384 + tid];
        (MODE == 0 ? g_Z : g_w)[b * NS + rt * 128 + tid] = s;
    }
}

// ---------------- u_part[b,chunk,:] = sum_{k in chunk} w[b,k] * X[b,k,:] ----------------
__global__ void accum_u_kernel(const float* __restrict__ X) {
    const int b = blockIdx.x >> 5, kc = blockIdx.x & 31;
    const int d = threadIdx.x;
    const float* Xg = X + ((size_t)b * NS + kc * 128) * 128;
    const float* wg = g_w + b * NS + kc * 128;
    float s = 0.0f;
    #pragma unroll 8
    for (int k = 0; k < 128; ++k) s = fmaf(wg[k], Xg[(size_t)k * 128 + d], s);
    g_upart[((size_t)b * NT + kc) * 128 + d] = s;
}

// ---------------- out[b,:] = (u[b,:] @ Wv) / S ----------------
__global__ void out_kernel(const float* __restrict__ Wv, float* __restrict__ out) {
    const int b = blockIdx.x;
    const int e = threadIdx.x;
    __shared__ float u[128];
    float us = 0.0f;
    #pragma unroll
    for (int c = 0; c < NT; ++c) us += g_upart[((size_t)b * NT + c) * 128 + threadIdx.x];
    u[threadIdx.x] = us;
    __syncthreads();
    float acc = 0.0f;
    #pragma unroll 8
    for (int d = 0; d < 128; ++d) acc = fmaf(u[d], Wv[d * 128 + e], acc);
    out[b * 128 + e] = acc * (1.0f / (float)NS);
}

// ---------------- launcher ----------------
extern "C" void kernel_launch(void* const* d_in, const int* in_sizes, int n_in,
                              void* d_out, int out_size) {
    int xi = 0, wi = 1;
    if (n_in >= 2 && in_sizes[0] == 3 * 128 * 128) { xi = 1; wi = 0; }
    const float* X = (const float*)d_in[xi];
    const float* W = (const float*)d_in[wi];
    float* out = (float*)d_out;

    cudaFuncSetAttribute(proj_kernel,   cudaFuncAttributeMaxDynamicSharedMemorySize, SM_PROJ);
    cudaFuncSetAttribute(score_pass<0>, cudaFuncAttributeMaxDynamicSharedMemorySize, SM_SCORE);
    cudaFuncSetAttribute(score_pass<1>, cudaFuncAttributeMaxDynamicSharedMemorySize, SM_SCORE);

    proj_kernel  <<<NTILES, 256, SM_PROJ>>>(X, W);
    score_pass<0><<<NTILES, 256, SM_SCORE>>>();
    score_pass<1><<<NTILES, 256, SM_SCORE>>>();
    accum_u_kernel<<<NB * NT, 128>>>(X);
    out_kernel   <<<NB, 128>>>(W + 2 * 128 * 128, out);
    (void)out_size;
}

// round 4
// speedup vs baseline: 2.8676x; 1.3037x over previous
#include <cuda_runtime.h>
#include <cuda_bf16.h>
#include <cstdint>

#define NB 8
#define NS 4096
#define ND 128
#define NT 32                 // NS / 128
#define TPITCH 129            // fp32 smem pitch (proj kernel)
#define NTILES (NB * NT)      // 256 row-tiles of flattened [B*S, D]
#define TILE_ELEMS 16384      // 128*128
#define PITCHB 272            // bf16 tile smem row pitch in BYTES (136 bf16)
#define TILEB (128 * PITCHB)  // 34816 bytes per padded tile

// ---------------- scratch (static device arrays; no allocations) ----------------
__device__ __nv_bfloat16 g_Qhi[NTILES * TILE_ELEMS];
__device__ __nv_bfloat16 g_Qlo[NTILES * TILE_ELEMS];
__device__ __nv_bfloat16 g_Khi[NTILES * TILE_ELEMS];   // pre-scaled by log2(e)
__device__ __nv_bfloat16 g_Klo[NTILES * TILE_ELEMS];
__device__ __nv_bfloat16 g_P[(size_t)NB * NS * NS];    // exp(scores), 268 MB
__device__ float g_Z[NB * NS];
__device__ float g_rz[NB * NS];
__device__ float g_w[NB * NS];
__device__ float g_upart[NB * NT * ND];

// ---------------- helpers ----------------
__device__ __forceinline__ uint32_t smem_u32(const void* p) {
    uint32_t a;
    asm("{ .reg .u64 t; cvta.to.shared.u64 t, %1; cvt.u32.u64 %0, t; }" : "=r"(a) : "l"(p));
    return a;
}
__device__ __forceinline__ void cpa16(uint32_t dst, const void* src) {
    asm volatile("cp.async.cg.shared.global [%0], [%1], 16;" :: "r"(dst), "l"(src));
}
__device__ __forceinline__ void cpa_commit() {
    asm volatile("cp.async.commit_group;" ::: "memory");
}
template<int N>
__device__ __forceinline__ void cpa_wait() {
    asm volatile("cp.async.wait_group %0;" :: "n"(N) : "memory");
}
__device__ __forceinline__ void ldsm_x4(uint32_t& r0, uint32_t& r1, uint32_t& r2, uint32_t& r3,
                                        uint32_t addr) {
    asm volatile("ldmatrix.sync.aligned.m8n8.x4.shared.b16 {%0,%1,%2,%3}, [%4];"
                 : "=r"(r0), "=r"(r1), "=r"(r2), "=r"(r3) : "r"(addr));
}
__device__ __forceinline__ void mma16816(float* c, const uint32_t* a, uint32_t b0, uint32_t b1) {
    asm volatile(
        "mma.sync.aligned.m16n8k16.row.col.f32.bf16.bf16.f32 "
        "{%0,%1,%2,%3}, {%4,%5,%6,%7}, {%8,%9}, {%0,%1,%2,%3};"
        : "+f"(c[0]), "+f"(c[1]), "+f"(c[2]), "+f"(c[3])
        : "r"(a[0]), "r"(a[1]), "r"(a[2]), "r"(a[3]), "r"(b0), "r"(b1));
}
__device__ __forceinline__ float ex2f(float x) {
    float r;
    asm("ex2.approx.f32 %0, %1;" : "=f"(r) : "f"(x));
    return r;
}

__device__ __forceinline__ void load_tile129(float* dst, const float* __restrict__ src, int tid) {
    #pragma unroll
    for (int it = 0; it < 16; ++it) {
        int idx = tid + it * 256;
        int row = idx >> 5;
        int c4  = (idx & 31) << 2;
        float4 v = *reinterpret_cast<const float4*>(src + (size_t)row * 128 + c4);
        float* p = dst + row * TPITCH + c4;
        p[0] = v.x; p[1] = v.y; p[2] = v.z; p[3] = v.w;
    }
}

// ---------------- projections: fp32 GEMM -> bf16 hi/lo row-major tiles ----------------
// K is pre-scaled by log2(e) so score accumulators arrive in the log2 domain.
#define SM_PROJ (128 * TPITCH * 4 + 65536)

__global__ void __launch_bounds__(256) proj_kernel(const float* __restrict__ X,
                                                   const float* __restrict__ Wqk) {
    extern __shared__ char smc[];
    float* Xs  = (float*)smc;
    float* Ws  = (float*)(smc + 128 * TPITCH * 4);
    char*  stg = smc + 128 * TPITCH * 4;     // aliases Ws after compute
    const int tid = threadIdx.x, tx = tid & 15, ty = tid >> 4;
    const size_t r0 = (size_t)blockIdx.x * 128;

    load_tile129(Xs, X + r0 * 128, tid);

    for (int w = 0; w < 2; ++w) {
        const float* Wg = Wqk + (size_t)w * TILE_ELEMS;
        #pragma unroll
        for (int it = 0; it < 16; ++it)
            reinterpret_cast<float4*>(Ws)[tid + it * 256] =
                reinterpret_cast<const float4*>(Wg)[tid + it * 256];
        __syncthreads();

        float acc[64];
        #pragma unroll
        for (int t = 0; t < 64; ++t) acc[t] = 0.0f;

        #pragma unroll 4
        for (int d = 0; d < 128; ++d) {
            float a[8], b[8];
            #pragma unroll
            for (int i = 0; i < 8; ++i) a[i] = Xs[(ty + 16 * i) * TPITCH + d];
            #pragma unroll
            for (int j = 0; j < 8; ++j) b[j] = Ws[d * 128 + tx + 16 * j];
            #pragma unroll
            for (int i = 0; i < 8; ++i)
                #pragma unroll
                for (int j = 0; j < 8; ++j)
                    acc[i * 8 + j] = fmaf(a[i], b[j], acc[i * 8 + j]);
        }
        __syncthreads();

        const float scale = (w == 0) ? 1.0f : 1.44269504088896341f;
        #pragma unroll
        for (int i = 0; i < 8; ++i)
            #pragma unroll
            for (int j = 0; j < 8; ++j) {
                float v = acc[i * 8 + j] * scale;
                __nv_bfloat16 hi = __float2bfloat16(v);
                __nv_bfloat16 lo = __float2bfloat16(v - __bfloat162float(hi));
                uint32_t o = (uint32_t)(ty + 16 * i) * 256 + (uint32_t)(tx + 16 * j) * 2;
                *(__nv_bfloat16*)(stg + o) = hi;
                *(__nv_bfloat16*)(stg + 32768 + o) = lo;
            }
        __syncthreads();

        __nv_bfloat16* dh = (w == 0 ? g_Qhi : g_Khi) + (size_t)blockIdx.x * TILE_ELEMS;
        __nv_bfloat16* dl = (w == 0 ? g_Qlo : g_Klo) + (size_t)blockIdx.x * TILE_ELEMS;
        #pragma unroll
        for (int it = 0; it < 8; ++it)
            reinterpret_cast<uint4*>(dh)[tid + it * 256] =
                reinterpret_cast<const uint4*>(stg)[tid + it * 256];
        #pragma unroll
        for (int it = 0; it < 8; ++it)
            reinterpret_cast<uint4*>(dl)[tid + it * 256] =
                reinterpret_cast<const uint4*>(stg + 32768)[tid + it * 256];
        __syncthreads();
    }
}

// ---------------- pass 1: p = exp(QK^T) stored bf16; Z[q] = row sums ----------------
#define O_RHI  0
#define O_RLO  TILEB
#define O_SB(buf) (2 * TILEB + (buf) * 2 * TILEB)
#define O_RED  (6 * TILEB)
#define SM_SCORE (O_RED + 2048)

// async-copy one 128x128 bf16 row-major tile into padded smem
__device__ __forceinline__ void tile_g2s(uint32_t dst, const __nv_bfloat16* src, int tid) {
    #pragma unroll
    for (int i = 0; i < 8; ++i) {
        int c = tid + i * 256;          // 2048 16B-chunks
        int row = c >> 4, col = c & 15;
        cpa16(dst + row * PITCHB + col * 16, (const char*)src + row * 256 + col * 16);
    }
}

__global__ void __launch_bounds__(256, 1) score_store() {
    extern __shared__ char smc[];
    const uint32_t sb = smem_u32(smc);
    const int tid = threadIdx.x, lane = tid & 31, warp = tid >> 5;
    const int warpM = warp & 1, warpN = warp >> 1;   // 2 x 4 warp grid; 64x32 per warp
    const int b = blockIdx.x >> 5, rt = blockIdx.x & 31;
    const int tile0 = b * NT;

    const __nv_bfloat16* Rhi = g_Qhi + (size_t)(tile0 + rt) * TILE_ELEMS;
    const __nv_bfloat16* Rlo = g_Qlo + (size_t)(tile0 + rt) * TILE_ELEMS;
    const __nv_bfloat16* Shi = g_Khi + (size_t)tile0 * TILE_ELEMS;
    const __nv_bfloat16* Slo = g_Klo + (size_t)tile0 * TILE_ELEMS;

    tile_g2s(sb + O_RHI, Rhi, tid);
    tile_g2s(sb + O_RLO, Rlo, tid);
    tile_g2s(sb + O_SB(0), Shi, tid);
    tile_g2s(sb + O_SB(0) + TILEB, Slo, tid);
    cpa_commit();
    tile_g2s(sb + O_SB(1), Shi + TILE_ELEMS, tid);
    tile_g2s(sb + O_SB(1) + TILEB, Slo + TILE_ELEMS, tid);
    cpa_commit();

    const uint32_t a_off = (uint32_t)(warpM * 64 + (lane & 15)) * PITCHB + (lane >> 4) * 16;
    const uint32_t b_off = (uint32_t)(warpN * 32 + (lane & 15)) * PITCHB + (lane >> 4) * 16;

    // p output base for this thread's fragment rows/cols
    const int row0 = warpM * 64 + (lane >> 2);          // + mt*16 + p8*8
    const int col0 = warpN * 32 + (lane & 3) * 2;       // + nt*8
    __nv_bfloat16* Pg = g_P + ((size_t)b * NS + (size_t)(rt * 128 + row0)) * NS + col0;

    float zp[8];
    #pragma unroll
    for (int i = 0; i < 8; ++i) zp[i] = 0.0f;

    for (int kt = 0; kt < NT; ++kt) {
        cpa_wait<1>();
        __syncthreads();

        float acc[16][4];
        #pragma unroll
        for (int t = 0; t < 16; ++t)
            #pragma unroll
            for (int r = 0; r < 4; ++r) acc[t][r] = 0.0f;

        const uint32_t sbuf = sb + O_SB(kt & 1);
        // split combos: (A,B) in {(hi,hi),(hi,lo),(lo,hi)}
        #pragma unroll
        for (int sp = 0; sp < 3; ++sp) {
            const uint32_t abase = sb + (sp == 2 ? O_RLO : O_RHI) + a_off;
            const uint32_t bbase = sbuf + (sp == 1 ? TILEB : 0) + b_off;
            #pragma unroll
            for (int ks = 0; ks < 8; ++ks) {
                uint32_t a[4][4];
                #pragma unroll
                for (int mt = 0; mt < 4; ++mt)
                    ldsm_x4(a[mt][0], a[mt][1], a[mt][2], a[mt][3],
                            abase + mt * 16 * PITCHB + ks * 32);
                uint32_t bb[4][2];
                #pragma unroll
                for (int nt2 = 0; nt2 < 2; ++nt2) {
                    uint32_t r0, r1, r2, r3;
                    ldsm_x4(r0, r1, r2, r3, bbase + nt2 * 16 * PITCHB + ks * 32);
                    bb[nt2 * 2 + 0][0] = r0; bb[nt2 * 2 + 0][1] = r2;
                    bb[nt2 * 2 + 1][0] = r1; bb[nt2 * 2 + 1][1] = r3;
                }
                #pragma unroll
                for (int mt = 0; mt < 4; ++mt)
                    #pragma unroll
                    for (int nt = 0; nt < 4; ++nt)
                        mma16816(acc[mt * 4 + nt], a[mt], bb[nt][0], bb[nt][1]);
            }
        }
        __syncthreads();                  // everyone done with ldmatrix on buf[kt&1]
        if (kt + 2 < NT) {
            tile_g2s(sb + O_SB(kt & 1),         Shi + (size_t)(kt + 2) * TILE_ELEMS, tid);
            tile_g2s(sb + O_SB(kt & 1) + TILEB, Slo + (size_t)(kt + 2) * TILE_ELEMS, tid);
            cpa_commit();
        } else {
            cpa_commit();                 // keep group count in lockstep for wait<1>
        }

        // epilogue: p = 2^acc (K pre-scaled by log2e), accumulate row sums, store p
        __nv_bfloat16* Pk = Pg + kt * 128;
        #pragma unroll
        for (int mt = 0; mt < 4; ++mt)
            #pragma unroll
            for (int p8 = 0; p8 < 2; ++p8) {
                float s = 0.0f;
                #pragma unroll
                for (int nt = 0; nt < 4; ++nt) {
                    float e0 = ex2f(acc[mt * 4 + nt][p8 * 2 + 0]);
                    float e1 = ex2f(acc[mt * 4 + nt][p8 * 2 + 1]);
                    s += e0 + e1;
                    __nv_bfloat162 pv = __floats2bfloat162_rn(e0, e1);
                    *reinterpret_cast<uint32_t*>(
                        Pk + (size_t)(mt * 16 + p8 * 8) * NS + nt * 8) =
                        *reinterpret_cast<uint32_t*>(&pv);
                }
                zp[mt * 2 + p8] += s;
            }
    }

    // lane reduction over column quads, then cross-warpN via smem
    float* red = (float*)(smc + O_RED);
    #pragma unroll
    for (int i = 0; i < 8; ++i) {
        float v = zp[i];
        v += __shfl_xor_sync(0xffffffffu, v, 1);
        v += __shfl_xor_sync(0xffffffffu, v, 2);
        int mt = i >> 1, p8 = i & 1;
        if ((lane & 3) == 0)
            red[warpN * 128 + warpM * 64 + mt * 16 + p8 * 8 + (lane >> 2)] = v;
    }
    __syncthreads();
    if (tid < 128) {
        float s = red[tid] + red[128 + tid] + red[256 + tid] + red[384 + tid];
        g_Z[b * NS + rt * 128 + tid] = s;
    }
}

// ---------------- rz = 1/Z ----------------
__global__ void rz_kernel() {
    int i = blockIdx.x * 1024 + threadIdx.x;
    g_rz[i] = 1.0f / g_Z[i];
}

// ---------------- w[b,k] = sum_q p[b,q,k] * rz[b,q]  (DRAM streaming) ----------------
__global__ void __launch_bounds__(256) colsum_kernel() {
    const int b = blockIdx.x >> 5, kc = blockIdx.x & 31;
    const int tid = threadIdx.x;
    const int tq = tid >> 6, tk = tid & 63;          // 4 q-groups x 64 threads (2 k each)
    const __nv_bfloat16* Pg = g_P + (size_t)b * NS * NS + (size_t)(kc * 128 + tk * 2);
    const float* rzp = g_rz + b * NS;
    float ax = 0.0f, ay = 0.0f;
    #pragma unroll 4
    for (int q = tq; q < NS; q += 4) {
        uint32_t pv = *reinterpret_cast<const uint32_t*>(Pg + (size_t)q * NS);
        float r = rzp[q];
        float2 f = __bfloat1622float2(*reinterpret_cast<const __nv_bfloat162*>(&pv));
        ax = fmaf(f.x, r, ax);
        ay = fmaf(f.y, r, ay);
    }
    __shared__ float red[4][128];
    red[tq][tk * 2 + 0] = ax;
    red[tq][tk * 2 + 1] = ay;
    __syncthreads();
    if (tid < 128) {
        float s = red[0][tid] + red[1][tid] + red[2][tid] + red[3][tid];
        g_w[b * NS + kc * 128 + tid] = s;
    }
}

// ---------------- u_part[b,chunk,:] = sum_{k in chunk} w[b,k] * X[b,k,:] ----------------
__global__ void accum_u_kernel(const float* __restrict__ X) {
    const int b = blockIdx.x >> 5, kc = blockIdx.x & 31;
    const int d = threadIdx.x;
    const float* Xg = X + ((size_t)b * NS + kc * 128) * 128;
    const float* wg = g_w + b * NS + kc * 128;
    float s = 0.0f;
    #pragma unroll 8
    for (int k = 0; k < 128; ++k) s = fmaf(wg[k], Xg[(size_t)k * 128 + d], s);
    g_upart[((size_t)b * NT + kc) * 128 + d] = s;
}

// ---------------- out[b,:] = (u[b,:] @ Wv) / S ----------------
__global__ void out_kernel(const float* __restrict__ Wv, float* __restrict__ out) {
    const int b = blockIdx.x;
    const int e = threadIdx.x;
    __shared__ float u[128];
    float us = 0.0f;
    #pragma unroll
    for (int c = 0; c < NT; ++c) us += g_upart[((size_t)b * NT + c) * 128 + threadIdx.x];
    u[threadIdx.x] = us;
    __syncthreads();
    float acc = 0.0f;
    #pragma unroll 8
    for (int d = 0; d < 128; ++d) acc = fmaf(u[d], Wv[d * 128 + e], acc);
    out[b * 128 + e] = acc * (1.0f / (float)NS);
}

// ---------------- launcher ----------------
extern "C" void kernel_launch(void* const* d_in, const int* in_sizes, int n_in,
                              void* d_out, int out_size) {
    int xi = 0, wi = 1;
    if (n_in >= 2 && in_sizes[0] == 3 * 128 * 128) { xi = 1; wi = 0; }
    const float* X = (const float*)d_in[xi];
    const float* W = (const float*)d_in[wi];
    float* out = (float*)d_out;

    cudaFuncSetAttribute(proj_kernel, cudaFuncAttributeMaxDynamicSharedMemorySize, SM_PROJ);
    cudaFuncSetAttribute(score_store, cudaFuncAttributeMaxDynamicSharedMemorySize, SM_SCORE);

    proj_kernel  <<<NTILES, 256, SM_PROJ>>>(X, W);
    score_store  <<<NTILES, 256, SM_SCORE>>>();
    rz_kernel    <<<NB * NS / 1024, 1024>>>();
    colsum_kernel<<<NB * NT, 256>>>();
    accum_u_kernel<<<NB * NT, 128>>>(X);
    out_kernel   <<<NB, 128>>>(W + 2 * 128 * 128, out);
    (void)out_size;
}

// round 5
// speedup vs baseline: 3.4706x; 1.2103x over previous
#include <cuda_runtime.h>
#include <cuda_bf16.h>
#include <cstdint>

#define NB 8
#define NS 4096
#define ND 128
#define NT 32                 // NS / 128
#define TPITCH 129            // fp32 smem pitch (proj kernel)
#define NTILES (NB * NT)      // 256 row-tiles of flattened [B*S, D]
#define TILE_ELEMS 16384      // 128*128
#define PITCHB 272            // bf16 tile smem row pitch in BYTES (136 bf16)
#define TILEB (128 * PITCHB)  // 34816 bytes per padded tile
#define QSPLIT 8              // colsum q-splits

// ---------------- scratch (static device arrays; no allocations) ----------------
__device__ __nv_bfloat16 g_Qhi[NTILES * TILE_ELEMS];
__device__ __nv_bfloat16 g_Qlo[NTILES * TILE_ELEMS];
__device__ __nv_bfloat16 g_Khi[NTILES * TILE_ELEMS];   // pre-scaled by log2(e)
__device__ __nv_bfloat16 g_Klo[NTILES * TILE_ELEMS];
__device__ __nv_bfloat16 g_P[(size_t)NB * NS * NS];    // exp(scores), col-permuted by g5
__device__ float g_Z[NB * NS];
__device__ float g_rz[NB * NS];
__device__ float g_w[NB * NS];
__device__ float g_wpart[QSPLIT * NB * NS];
__device__ float g_upart[NB * NT * ND];

// ---------------- helpers ----------------
__device__ __forceinline__ uint32_t smem_u32(const void* p) {
    uint32_t a;
    asm("{ .reg .u64 t; cvta.to.shared.u64 t, %1; cvt.u32.u64 %0, t; }" : "=r"(a) : "l"(p));
    return a;
}
__device__ __forceinline__ void cpa16(uint32_t dst, const void* src) {
    asm volatile("cp.async.cg.shared.global [%0], [%1], 16;" :: "r"(dst), "l"(src));
}
__device__ __forceinline__ void cpa_commit() {
    asm volatile("cp.async.commit_group;" ::: "memory");
}
template<int N>
__device__ __forceinline__ void cpa_wait() {
    asm volatile("cp.async.wait_group %0;" :: "n"(N) : "memory");
}
__device__ __forceinline__ void ldsm_x4(uint32_t& r0, uint32_t& r1, uint32_t& r2, uint32_t& r3,
                                        uint32_t addr) {
    asm volatile("ldmatrix.sync.aligned.m8n8.x4.shared.b16 {%0,%1,%2,%3}, [%4];"
                 : "=r"(r0), "=r"(r1), "=r"(r2), "=r"(r3) : "r"(addr));
}
__device__ __forceinline__ void mma16816(float* c, const uint32_t* a, uint32_t b0, uint32_t b1) {
    asm volatile(
        "mma.sync.aligned.m16n8k16.row.col.f32.bf16.bf16.f32 "
        "{%0,%1,%2,%3}, {%4,%5,%6,%7}, {%8,%9}, {%0,%1,%2,%3};"
        : "+f"(c[0]), "+f"(c[1]), "+f"(c[2]), "+f"(c[3])
        : "r"(a[0]), "r"(a[1]), "r"(a[2]), "r"(a[3]), "r"(b0), "r"(b1));
}
__device__ __forceinline__ float ex2f(float x) {
    float r;
    asm("ex2.approx.f32 %0, %1;" : "=f"(r) : "f"(x));
    return r;
}
// involution mapping P-memory column <-> fragment column within a 32-col group
__device__ __forceinline__ int g5(int j) {
    return ((j & 7) >> 1) * 8 + (j >> 3) * 2 + (j & 1);
}

__device__ __forceinline__ void load_tile129(float* dst, const float* __restrict__ src, int tid) {
    #pragma unroll
    for (int it = 0; it < 16; ++it) {
        int idx = tid + it * 256;
        int row = idx >> 5;
        int c4  = (idx & 31) << 2;
        float4 v = *reinterpret_cast<const float4*>(src + (size_t)row * 128 + c4);
        float* p = dst + row * TPITCH + c4;
        p[0] = v.x; p[1] = v.y; p[2] = v.z; p[3] = v.w;
    }
}

// ---------------- projections: fp32 GEMM -> bf16 hi/lo row-major tiles ----------------
#define SM_PROJ (128 * TPITCH * 4 + 65536)

__global__ void __launch_bounds__(256) proj_kernel(const float* __restrict__ X,
                                                   const float* __restrict__ Wqk) {
    extern __shared__ char smc[];
    float* Xs  = (float*)smc;
    float* Ws  = (float*)(smc + 128 * TPITCH * 4);
    char*  stg = smc + 128 * TPITCH * 4;     // aliases Ws after compute
    const int tid = threadIdx.x, tx = tid & 15, ty = tid >> 4;
    const size_t r0 = (size_t)blockIdx.x * 128;

    load_tile129(Xs, X + r0 * 128, tid);

    for (int w = 0; w < 2; ++w) {
        const float* Wg = Wqk + (size_t)w * TILE_ELEMS;
        #pragma unroll
        for (int it = 0; it < 16; ++it)
            reinterpret_cast<float4*>(Ws)[tid + it * 256] =
                reinterpret_cast<const float4*>(Wg)[tid + it * 256];
        __syncthreads();

        float acc[64];
        #pragma unroll
        for (int t = 0; t < 64; ++t) acc[t] = 0.0f;

        #pragma unroll 4
        for (int d = 0; d < 128; ++d) {
            float a[8], b[8];
            #pragma unroll
            for (int i = 0; i < 8; ++i) a[i] = Xs[(ty + 16 * i) * TPITCH + d];
            #pragma unroll
            for (int j = 0; j < 8; ++j) b[j] = Ws[d * 128 + tx + 16 * j];
            #pragma unroll
            for (int i = 0; i < 8; ++i)
                #pragma unroll
                for (int j = 0; j < 8; ++j)
                    acc[i * 8 + j] = fmaf(a[i], b[j], acc[i * 8 + j]);
        }
        __syncthreads();

        const float scale = (w == 0) ? 1.0f : 1.44269504088896341f;
        #pragma unroll
        for (int i = 0; i < 8; ++i)
            #pragma unroll
            for (int j = 0; j < 8; ++j) {
                float v = acc[i * 8 + j] * scale;
                __nv_bfloat16 hi = __float2bfloat16(v);
                __nv_bfloat16 lo = __float2bfloat16(v - __bfloat162float(hi));
                uint32_t o = (uint32_t)(ty + 16 * i) * 256 + (uint32_t)(tx + 16 * j) * 2;
                *(__nv_bfloat16*)(stg + o) = hi;
                *(__nv_bfloat16*)(stg + 32768 + o) = lo;
            }
        __syncthreads();

        __nv_bfloat16* dh = (w == 0 ? g_Qhi : g_Khi) + (size_t)blockIdx.x * TILE_ELEMS;
        __nv_bfloat16* dl = (w == 0 ? g_Qlo : g_Klo) + (size_t)blockIdx.x * TILE_ELEMS;
        #pragma unroll
        for (int it = 0; it < 8; ++it)
            reinterpret_cast<uint4*>(dh)[tid + it * 256] =
                reinterpret_cast<const uint4*>(stg)[tid + it * 256];
        #pragma unroll
        for (int it = 0; it < 8; ++it)
            reinterpret_cast<uint4*>(dl)[tid + it * 256] =
                reinterpret_cast<const uint4*>(stg + 32768)[tid + it * 256];
        __syncthreads();
    }
}

// ---------------- pass 1: p = exp(QK^T) stored bf16 (col-permuted); Z = row sums ----------------
#define O_RHI  0
#define O_RLO  TILEB
#define O_SB(buf) (2 * TILEB + (buf) * 2 * TILEB)
#define O_RED  (6 * TILEB)
#define SM_SCORE (O_RED + 2048)

__device__ __forceinline__ void tile_g2s(uint32_t dst, const __nv_bfloat16* src, int tid) {
    #pragma unroll
    for (int i = 0; i < 8; ++i) {
        int c = tid + i * 256;          // 2048 16B-chunks
        int row = c >> 4, col = c & 15;
        cpa16(dst + row * PITCHB + col * 16, (const char*)src + row * 256 + col * 16);
    }
}

__global__ void __launch_bounds__(256, 1) score_store() {
    extern __shared__ char smc[];
    const uint32_t sb = smem_u32(smc);
    const int tid = threadIdx.x, lane = tid & 31, warp = tid >> 5;
    const int warpM = warp & 1, warpN = warp >> 1;   // 2 x 4 warp grid; 64x32 per warp
    const int b = blockIdx.x >> 5, rt = blockIdx.x & 31;
    const int tile0 = b * NT;

    const __nv_bfloat16* Rhi = g_Qhi + (size_t)(tile0 + rt) * TILE_ELEMS;
    const __nv_bfloat16* Rlo = g_Qlo + (size_t)(tile0 + rt) * TILE_ELEMS;
    const __nv_bfloat16* Shi = g_Khi + (size_t)tile0 * TILE_ELEMS;
    const __nv_bfloat16* Slo = g_Klo + (size_t)tile0 * TILE_ELEMS;

    tile_g2s(sb + O_RHI, Rhi, tid);
    tile_g2s(sb + O_RLO, Rlo, tid);
    tile_g2s(sb + O_SB(0), Shi, tid);
    tile_g2s(sb + O_SB(0) + TILEB, Slo, tid);
    cpa_commit();
    tile_g2s(sb + O_SB(1), Shi + TILE_ELEMS, tid);
    tile_g2s(sb + O_SB(1) + TILEB, Slo + TILE_ELEMS, tid);
    cpa_commit();

    const uint32_t a_off = (uint32_t)(warpM * 64 + (lane & 15)) * PITCHB + (lane >> 4) * 16;
    const uint32_t b_off = (uint32_t)(warpN * 32 + (lane & 15)) * PITCHB + (lane >> 4) * 16;

    // P output: permuted layout -> each thread owns 8 CONTIGUOUS mem columns
    const int row0 = warpM * 64 + (lane >> 2);          // + mt*16 + p8*8
    const int col0 = warpN * 32 + (lane & 3) * 8;       // 16B-aligned
    __nv_bfloat16* Pg = g_P + ((size_t)b * NS + (size_t)(rt * 128 + row0)) * NS + col0;

    float zp[8];
    #pragma unroll
    for (int i = 0; i < 8; ++i) zp[i] = 0.0f;

    for (int kt = 0; kt < NT; ++kt) {
        cpa_wait<1>();
        __syncthreads();

        float acc[16][4];
        #pragma unroll
        for (int t = 0; t < 16; ++t)
            #pragma unroll
            for (int r = 0; r < 4; ++r) acc[t][r] = 0.0f;

        const uint32_t sbuf = sb + O_SB(kt & 1);
        #pragma unroll
        for (int sp = 0; sp < 3; ++sp) {
            const uint32_t abase = sb + (sp == 2 ? O_RLO : O_RHI) + a_off;
            const uint32_t bbase = sbuf + (sp == 1 ? TILEB : 0) + b_off;
            #pragma unroll
            for (int ks = 0; ks < 8; ++ks) {
                uint32_t a[4][4];
                #pragma unroll
                for (int mt = 0; mt < 4; ++mt)
                    ldsm_x4(a[mt][0], a[mt][1], a[mt][2], a[mt][3],
                            abase + mt * 16 * PITCHB + ks * 32);
                uint32_t bb[4][2];
                #pragma unroll
                for (int nt2 = 0; nt2 < 2; ++nt2) {
                    uint32_t r0, r1, r2, r3;
                    ldsm_x4(r0, r1, r2, r3, bbase + nt2 * 16 * PITCHB + ks * 32);
                    bb[nt2 * 2 + 0][0] = r0; bb[nt2 * 2 + 0][1] = r2;
                    bb[nt2 * 2 + 1][0] = r1; bb[nt2 * 2 + 1][1] = r3;
                }
                #pragma unroll
                for (int mt = 0; mt < 4; ++mt)
                    #pragma unroll
                    for (int nt = 0; nt < 4; ++nt)
                        mma16816(acc[mt * 4 + nt], a[mt], bb[nt][0], bb[nt][1]);
            }
        }
        __syncthreads();
        if (kt + 2 < NT) {
            tile_g2s(sb + O_SB(kt & 1),         Shi + (size_t)(kt + 2) * TILE_ELEMS, tid);
            tile_g2s(sb + O_SB(kt & 1) + TILEB, Slo + (size_t)(kt + 2) * TILE_ELEMS, tid);
            cpa_commit();
        } else {
            cpa_commit();
        }

        // epilogue: p = 2^acc; accumulate row sums; one 16B store per (mt,p8) row
        __nv_bfloat16* Pk = Pg + kt * 128;
        #pragma unroll
        for (int mt = 0; mt < 4; ++mt)
            #pragma unroll
            for (int p8 = 0; p8 < 2; ++p8) {
                float s = 0.0f;
                uint32_t pv[4];
                #pragma unroll
                for (int nt = 0; nt < 4; ++nt) {
                    float e0 = ex2f(acc[mt * 4 + nt][p8 * 2 + 0]);
                    float e1 = ex2f(acc[mt * 4 + nt][p8 * 2 + 1]);
                    s += e0 + e1;
                    __nv_bfloat162 p2 = __floats2bfloat162_rn(e0, e1);
                    pv[nt] = *reinterpret_cast<uint32_t*>(&p2);
                }
                zp[mt * 2 + p8] += s;
                uint4 v = make_uint4(pv[0], pv[1], pv[2], pv[3]);
                *reinterpret_cast<uint4*>(Pk + (size_t)(mt * 16 + p8 * 8) * NS) = v;
            }
    }

    // lane reduction over column quads, then cross-warpN via smem
    float* red = (float*)(smc + O_RED);
    #pragma unroll
    for (int i = 0; i < 8; ++i) {
        float v = zp[i];
        v += __shfl_xor_sync(0xffffffffu, v, 1);
        v += __shfl_xor_sync(0xffffffffu, v, 2);
        int mt = i >> 1, p8 = i & 1;
        if ((lane & 3) == 0)
            red[warpN * 128 + warpM * 64 + mt * 16 + p8 * 8 + (lane >> 2)] = v;
    }
    __syncthreads();
    if (tid < 128) {
        float s = red[tid] + red[128 + tid] + red[256 + tid] + red[384 + tid];
        g_Z[b * NS + rt * 128 + tid] = s;
    }
}

// ---------------- rz = 1/Z ----------------
__global__ void rz_kernel() {
    int i = blockIdx.x * 1024 + threadIdx.x;
    g_rz[i] = 1.0f / g_Z[i];
}

// ---------------- colsum partials: 8 q-splits for occupancy ----------------
// grid = NB*NT*QSPLIT: bi -> b = bi>>8, kc = (bi>>3)&31, qs = bi&7
__global__ void __launch_bounds__(256) colsum_kernel() {
    const int b = blockIdx.x >> 8, kc = (blockIdx.x >> 3) & 31, qs = blockIdx.x & 7;
    const int tid = threadIdx.x;
    const int tq = tid >> 6, tk = tid & 63;          // 4 q-groups x 64 threads (2 cols each)
    const int q0 = qs * (NS / QSPLIT);
    const __nv_bfloat16* Pg = g_P + ((size_t)b * NS + q0) * NS + (size_t)(kc * 128 + tk * 2);
    const float* rzp = g_rz + b * NS + q0;
    float ax = 0.0f, ay = 0.0f;
    #pragma unroll 8
    for (int q = tq; q < NS / QSPLIT; q += 4) {
        uint32_t pv = *reinterpret_cast<const uint32_t*>(Pg + (size_t)q * NS);
        float r = rzp[q];
        float2 f = __bfloat1622float2(*reinterpret_cast<const __nv_bfloat162*>(&pv));
        ax = fmaf(f.x, r, ax);
        ay = fmaf(f.y, r, ay);
    }
    __shared__ float red[4][128];
    red[tq][tk * 2 + 0] = ax;
    red[tq][tk * 2 + 1] = ay;
    __syncthreads();
    if (tid < 128) {
        float s = red[0][tid] + red[1][tid] + red[2][tid] + red[3][tid];
        g_wpart[(size_t)qs * (NB * NS) + b * NS + kc * 128 + tid] = s;
    }
}

// ---------------- wred: sum partials, undo column permutation ----------------
__global__ void wred_kernel() {
    int i = blockIdx.x * 1024 + threadIdx.x;        // 0 .. NB*NS-1 (P-memory index)
    float s = 0.0f;
    #pragma unroll
    for (int qs = 0; qs < QSPLIT; ++qs) s += g_wpart[(size_t)qs * (NB * NS) + i];
    int logical = (i & ~31) | g5(i & 31);
    g_w[logical] = s;
}

// ---------------- u_part[b,chunk,:] = sum_{k in chunk} w[b,k] * X[b,k,:] ----------------
__global__ void accum_u_kernel(const float* __restrict__ X) {
    const int b = blockIdx.x >> 5, kc = blockIdx.x & 31;
    const int d = threadIdx.x;
    const float* Xg = X + ((size_t)b * NS + kc * 128) * 128;
    const float* wg = g_w + b * NS + kc * 128;
    float s = 0.0f;
    #pragma unroll 8
    for (int k = 0; k < 128; ++k) s = fmaf(wg[k], Xg[(size_t)k * 128 + d], s);
    g_upart[((size_t)b * NT + kc) * 128 + d] = s;
}

// ---------------- out[b,:] = (u[b,:] @ Wv) / S ----------------
__global__ void out_kernel(const float* __restrict__ Wv, float* __restrict__ out) {
    const int b = blockIdx.x;
    const int e = threadIdx.x;
    __shared__ float u[128];
    float us = 0.0f;
    #pragma unroll
    for (int c = 0; c < NT; ++c) us += g_upart[((size_t)b * NT + c) * 128 + threadIdx.x];
    u[threadIdx.x] = us;
    __syncthreads();
    float acc = 0.0f;
    #pragma unroll 8
    for (int d = 0; d < 128; ++d) acc = fmaf(u[d], Wv[d * 128 + e], acc);
    out[b * 128 + e] = acc * (1.0f / (float)NS);
}

// ---------------- launcher ----------------
extern "C" void kernel_launch(void* const* d_in, const int* in_sizes, int n_in,
                              void* d_out, int out_size) {
    int xi = 0, wi = 1;
    if (n_in >= 2 && in_sizes[0] == 3 * 128 * 128) { xi = 1; wi = 0; }
    const float* X = (const float*)d_in[xi];
    const float* W = (const float*)d_in[wi];
    float* out = (float*)d_out;

    cudaFuncSetAttribute(proj_kernel, cudaFuncAttributeMaxDynamicSharedMemorySize, SM_PROJ);
    cudaFuncSetAttribute(score_store, cudaFuncAttributeMaxDynamicSharedMemorySize, SM_SCORE);

    proj_kernel  <<<NTILES, 256, SM_PROJ>>>(X, W);
    score_store  <<<NTILES, 256, SM_SCORE>>>();
    rz_kernel    <<<NB * NS / 1024, 1024>>>();
    colsum_kernel<<<NB * NT * QSPLIT, 256>>>();
    wred_kernel  <<<NB * NS / 1024, 1024>>>();
    accum_u_kernel<<<NB * NT, 128>>>(X);
    out_kernel   <<<NB, 128>>>(W + 2 * 128 * 128, out);
    (void)out_size;
}